// round 13
// baseline (speedup 1.0000x reference)
#include <cuda_runtime.h>
#include <cuda_bf16.h>
#include <cuda_fp16.h>
#include <math.h>
#include <stdint.h>

#define B_    8
#define N_    4096
#define CIN   256
#define CQK   32
#define NROWS (B_ * N_)   // 32768
#define QW    32          // q store: fp16 (log2e-scaled)
#define KW    32          // k store: fp16
#define NCHUNK (N_ / 128) // 32
#define LOG2E 1.4426950408889634f

// ---- scratch (device globals; no allocation allowed) ----
__device__ __half g_qs[NROWS * QW];   // 2 MB
__device__ __half g_ks[NROWS * KW];   // 2 MB
__device__ __half g_wh[64 * CIN];     // W split hi: [n][k] (n: Wq cols | Wk cols)
__device__ __half g_wl[64 * CIN];     // W split lo
__device__ __nv_bfloat16 g_vbh[NROWS];  // vbar hi (bf16)
__device__ __nv_bfloat16 g_vbl[NROWS];  // vbar lo residual (bf16)
__device__ float g_xbar[NROWS];
__device__ float g_wvbar[CIN];
__device__ float g_bvbar;

// =========================== PTX helpers ===================================
__device__ __forceinline__ uint32_t smem_u32(const void* p) {
    uint32_t a;
    asm("{ .reg .u64 t; cvta.to.shared.u64 t, %1; cvt.u32.u64 %0, t; }"
        : "=r"(a) : "l"(p));
    return a;
}
__device__ __forceinline__ void cp_async16(void* dst, const void* src) {
    uint32_t d = smem_u32(dst);
    asm volatile("cp.async.cg.shared.global [%0], [%1], 16;" :: "r"(d), "l"(src) : "memory");
}
#define CP_COMMIT()  asm volatile("cp.async.commit_group;" ::: "memory")
#define CP_WAIT(n)   asm volatile("cp.async.wait_group %0;" :: "n"(n) : "memory")

__device__ __forceinline__ void ldsm_x4(uint32_t& r0, uint32_t& r1,
                                        uint32_t& r2, uint32_t& r3, uint32_t a) {
    asm volatile("ldmatrix.sync.aligned.m8n8.x4.shared.b16 {%0,%1,%2,%3}, [%4];"
        : "=r"(r0), "=r"(r1), "=r"(r2), "=r"(r3) : "r"(a));
}
__device__ __forceinline__ void mma_f16(float& d0, float& d1, float& d2, float& d3,
    uint32_t a0, uint32_t a1, uint32_t a2, uint32_t a3,
    uint32_t b0, uint32_t b1,
    float c0, float c1, float c2, float c3) {
    asm volatile("mma.sync.aligned.m16n8k16.row.col.f32.f16.f16.f32 "
        "{%0,%1,%2,%3},{%4,%5,%6,%7},{%8,%9},{%10,%11,%12,%13};"
        : "=f"(d0), "=f"(d1), "=f"(d2), "=f"(d3)
        : "r"(a0), "r"(a1), "r"(a2), "r"(a3), "r"(b0), "r"(b1),
          "f"(c0), "f"(c1), "f"(c2), "f"(c3));
}
__device__ __forceinline__ void mma_bf16(float& d0, float& d1, float& d2, float& d3,
    uint32_t a0, uint32_t a1, uint32_t a2, uint32_t a3,
    uint32_t b0, uint32_t b1,
    float c0, float c1, float c2, float c3) {
    asm volatile("mma.sync.aligned.m16n8k16.row.col.f32.bf16.bf16.f32 "
        "{%0,%1,%2,%3},{%4,%5,%6,%7},{%8,%9},{%10,%11,%12,%13};"
        : "=f"(d0), "=f"(d1), "=f"(d2), "=f"(d3)
        : "r"(a0), "r"(a1), "r"(a2), "r"(a3), "r"(b0), "r"(b1),
          "f"(c0), "f"(c1), "f"(c2), "f"(c3));
}
__device__ __forceinline__ float ex2f(float x) {
    float r;
    asm("ex2.approx.f32 %0, %1;" : "=f"(r) : "f"(x));
    return r;
}
__device__ __forceinline__ uint32_t cvt_bf2(float hi, float lo) {
    uint32_t r;
    asm("cvt.rn.bf16x2.f32 %0, %1, %2;" : "=r"(r) : "f"(hi), "f"(lo));
    return r;
}
__device__ __forceinline__ uint32_t pack_h2(float a, float b) {
    __half2 t = __floats2half2_rn(a, b);
    return *reinterpret_cast<uint32_t*>(&t);
}

// =========================== prep kernel ===================================
__global__ __launch_bounds__(256) void prep_kernel(
    const float* __restrict__ Wv, const float* __restrict__ bv,
    const float* __restrict__ Wq, const float* __restrict__ Wk) {
    const int wid = threadIdx.x >> 5, lane = threadIdx.x & 31;
    const int row = blockIdx.x * 8 + wid;
    const float* wr = Wv + (size_t)row * CIN;
    float s = 0.f;
    #pragma unroll
    for (int j = 0; j < 8; j++) s += wr[lane + j * 32];
    #pragma unroll
    for (int off = 16; off > 0; off >>= 1)
        s += __shfl_xor_sync(0xffffffffu, s, off);
    if (lane == 0) g_wvbar[row] = s * (1.f / CIN);

    if (blockIdx.x == 0 && wid == 0) {
        float t = 0.f;
        #pragma unroll
        for (int j = 0; j < 8; j++) t += bv[lane + j * 32];
        #pragma unroll
        for (int off = 16; off > 0; off >>= 1)
            t += __shfl_xor_sync(0xffffffffu, t, off);
        if (lane == 0) g_bvbar = t * (1.f / CIN);
    }

    if (blockIdx.x < 8) {
        const int n = blockIdx.x * 8 + wid;
        const float* wsrc = (n < 32) ? (Wq + n) : (Wk + n - 32);
        #pragma unroll
        for (int j = 0; j < 8; j++) {
            int k = lane + j * 32;
            float v = wsrc[(size_t)k * CQK];
            __half h = __float2half_rn(v);
            g_wh[n * CIN + k] = h;
            g_wl[n * CIN + k] = __float2half_rn(v - __half2float(h));
        }
    }
}

// ======================= Q/K projection GEMM (tensor core) ==================
// 2-term exact fp16-x split: x_hi*W_hi + x_hi*W_lo  (== x_f16 @ W exactly)
#define QPITCH 144
#define OFF_XH 0
#define OFF_WHS 18432
#define OFF_WLS 27648
#define OFF_WVS 36864
#define QK_SMEM 37888

__global__ __launch_bounds__(256, 3) void qk_gemm(
    const float* __restrict__ x,
    const float* __restrict__ bq, const float* __restrict__ bk) {

    extern __shared__ __align__(16) char smem[];
    const uint32_t sb = smem_u32(smem);
    const int tid = threadIdx.x, w = tid >> 5, lane = tid & 31;
    const int m0 = blockIdx.x * 128;

    ((float*)(smem + OFF_WVS))[tid] = g_wvbar[tid];
    __syncthreads();

    float c[8][4];
    #pragma unroll
    for (int i = 0; i < 8; i++)
        #pragma unroll
        for (int j = 0; j < 4; j++) c[i][j] = 0.f;
    float sxr[8], svr[8];
    #pragma unroll
    for (int t = 0; t < 8; t++) { sxr[t] = 0.f; svr[t] = 0.f; }

    const uint32_t abh = sb + OFF_XH + (w * 16 + (lane & 15)) * QPITCH + (lane >> 4) * 16;
    const uint32_t bbh = sb + OFF_WHS + (lane & 7) * QPITCH + (lane >> 3) * 16;
    const uint32_t bbl = sb + OFF_WLS + (lane & 7) * QPITCH + (lane >> 3) * 16;
    const float* wvs = (const float*)(smem + OFF_WVS);

    for (int kc = 0; kc < 4; kc++) {
        #pragma unroll
        for (int t = 0; t < 2; t++) {
            int s2 = t * 256 + tid;
            int n = s2 >> 3, seg = s2 & 7;
            *(uint4*)(smem + OFF_WHS + n * QPITCH + seg * 16) =
                *(const uint4*)(g_wh + n * CIN + kc * 64 + seg * 8);
            *(uint4*)(smem + OFF_WLS + n * QPITCH + seg * 16) =
                *(const uint4*)(g_wl + n * CIN + kc * 64 + seg * 8);
        }
        #pragma unroll
        for (int t = 0; t < 8; t++) {
            int row = t * 16 + (tid >> 4), seg = tid & 15;
            float4 xv = *(const float4*)(x + (size_t)(m0 + row) * CIN + kc * 64 + seg * 4);
            float4 wv = *(const float4*)(wvs + kc * 64 + seg * 4);
            sxr[t] += (xv.x + xv.y) + (xv.z + xv.w);
            svr[t] = fmaf(xv.x, wv.x, fmaf(xv.y, wv.y,
                     fmaf(xv.z, wv.z, fmaf(xv.w, wv.w, svr[t]))));
            *(uint2*)(smem + OFF_XH + row * QPITCH + seg * 8) =
                make_uint2(pack_h2(xv.x, xv.y), pack_h2(xv.z, xv.w));
        }
        __syncthreads();

        #pragma unroll
        for (int kc2 = 0; kc2 < 2; kc2++) {
            uint32_t ah0[4], ah1[4];
            ldsm_x4(ah0[0], ah0[1], ah0[2], ah0[3], abh + kc2 * 64);
            ldsm_x4(ah1[0], ah1[1], ah1[2], ah1[3], abh + kc2 * 64 + 32);
            #pragma unroll
            for (int nt = 0; nt < 8; nt++) {
                uint32_t bh[4], bl[4];
                ldsm_x4(bh[0], bh[1], bh[2], bh[3], bbh + nt * 8 * QPITCH + kc2 * 64);
                ldsm_x4(bl[0], bl[1], bl[2], bl[3], bbl + nt * 8 * QPITCH + kc2 * 64);
                mma_f16(c[nt][0], c[nt][1], c[nt][2], c[nt][3],
                        ah0[0], ah0[1], ah0[2], ah0[3], bh[0], bh[1],
                        c[nt][0], c[nt][1], c[nt][2], c[nt][3]);
                mma_f16(c[nt][0], c[nt][1], c[nt][2], c[nt][3],
                        ah1[0], ah1[1], ah1[2], ah1[3], bh[2], bh[3],
                        c[nt][0], c[nt][1], c[nt][2], c[nt][3]);
                mma_f16(c[nt][0], c[nt][1], c[nt][2], c[nt][3],
                        ah0[0], ah0[1], ah0[2], ah0[3], bl[0], bl[1],
                        c[nt][0], c[nt][1], c[nt][2], c[nt][3]);
                mma_f16(c[nt][0], c[nt][1], c[nt][2], c[nt][3],
                        ah1[0], ah1[1], ah1[2], ah1[3], bl[2], bl[3],
                        c[nt][0], c[nt][1], c[nt][2], c[nt][3]);
            }
        }
        __syncthreads();
    }

    // vbar / xbar writeback (vbar hi/lo bf16 split)
    #pragma unroll
    for (int t = 0; t < 8; t++) {
        float sx = sxr[t], sv = svr[t];
        #pragma unroll
        for (int off = 1; off < 16; off <<= 1) {
            sx += __shfl_xor_sync(0xffffffffu, sx, off);
            sv += __shfl_xor_sync(0xffffffffu, sv, off);
        }
        if ((lane & 15) == 0) {
            int row = m0 + t * 16 + (tid >> 4);
            float vb = sv + g_bvbar;
            __nv_bfloat16 h = __float2bfloat16_rn(vb);
            g_vbh[row] = h;
            g_vbl[row] = __float2bfloat16_rn(vb - __bfloat162float(h));
            g_xbar[row] = sx * (1.f / CIN);
        }
    }

    // epilogue: bias, (Q: log2e scale), fp16 stores
    const int r0 = lane >> 2;
    const int cl = (lane & 3) * 2;
    const size_t grow = (size_t)m0 + w * 16 + r0;
    #pragma unroll
    for (int nt = 0; nt < 8; nt++) {
        const int n = nt * 8 + cl;
        if (n < 32) {
            float2 bb = *(const float2*)(bq + n);
            #pragma unroll
            for (int half = 0; half < 2; half++) {
                size_t row = grow + half * 8;
                *(uint32_t*)(g_qs + row * QW + n) =
                    pack_h2((c[nt][2 * half + 0] + bb.x) * LOG2E,
                            (c[nt][2 * half + 1] + bb.y) * LOG2E);
            }
        } else {
            float2 bb = *(const float2*)(bk + n - 32);
            #pragma unroll
            for (int half = 0; half < 2; half++) {
                size_t row = grow + half * 8;
                *(uint32_t*)(g_ks + row * KW + n - 32) =
                    pack_h2(c[nt][2 * half + 0] + bb.x, c[nt][2 * half + 1] + bb.y);
            }
        }
    }
}

// =========================== attention kernel ==============================
// 512 threads: warp pairs (w, w+8) share 16 q-rows, split keys 0-63 / 64-127.
// smem: vb_hi(8K) + vb_lo(8K) + ring-4 K tiles [128 rows][40 fp16] (80-B pitch)
#define TPITCH   80
#define TILE_B   (128 * TPITCH)      // 10240
#define OFF_VH   0
#define OFF_VL   8192
#define OFF_K0   16384
#define SMEM_TOT (OFF_K0 + 4 * TILE_B)  // 57344

__global__ __launch_bounds__(512, 2) void attn_kernel(
    const float* __restrict__ gamma, float* __restrict__ out) {

    extern __shared__ __align__(16) char smem[];
    const uint32_t sb = smem_u32(smem);
    const int tid = threadIdx.x, wid = tid >> 5, lane = tid & 31;
    const int kw = wid >> 3;          // key half 0/1
    const int wr = wid & 7;           // row group (16 rows)
    const int b = blockIdx.y, n0 = blockIdx.x * 128;

    // per-thread cp.async offset for a 128x32 fp16 tile (512 16B segs, 1/thread)
    const int  boff = (tid >> 2) * TPITCH + (tid & 3) * 16;
    const long soff = (long)(tid >> 2) * KW + (tid & 3) * 8;

    const __half* ksrc = g_ks + (size_t)b * N_ * KW;

    // prologue: g0 = VH + VL + K0 ; g1 = K1 ; g2 = K2
    cp_async16(smem + OFF_VH + tid * 16, g_vbh + (size_t)b * N_ + tid * 8);
    cp_async16(smem + OFF_VL + tid * 16, g_vbl + (size_t)b * N_ + tid * 8);
    cp_async16(smem + OFF_K0 + boff, ksrc + soff);
    CP_COMMIT();
    cp_async16(smem + OFF_K0 + TILE_B + boff, ksrc + (size_t)128 * KW + soff);
    CP_COMMIT();
    cp_async16(smem + OFF_K0 + 2 * TILE_B + boff, ksrc + (size_t)256 * KW + soff);
    CP_COMMIT();

    // persistent q fragments (fp16, m16n8k16 A layout), rows wr*16..+15
    uint32_t A[2][4];
    {
        const __half* q0 =
            g_qs + ((size_t)b * N_ + n0 + wr * 16 + (lane >> 2)) * QW + (lane & 3) * 2;
        #pragma unroll
        for (int s = 0; s < 2; s++) {
            A[s][0] = *(const uint32_t*)(q0 + s * 16);
            A[s][1] = *(const uint32_t*)(q0 + s * 16 + 8 * QW);
            A[s][2] = *(const uint32_t*)(q0 + s * 16 + 8);
            A[s][3] = *(const uint32_t*)(q0 + s * 16 + 8 * QW + 8);
        }
    }

    // dual PV accumulators (even/odd s) to break the serial MMA chain
    float e0 = 0.f, e1 = 0.f, e2 = 0.f, e3 = 0.f;
    float f0 = 0.f, f1 = 0.f, f2 = 0.f, f3 = 0.f;

    const int nn = lane >> 2;
    const __nv_bfloat16* vbase =
        (nn == 0) ? (const __nv_bfloat16*)(smem + OFF_VH)
                  : (const __nv_bfloat16*)(smem + OFF_VL);
    const uint32_t bconst = (nn == 2) ? 0x3F803F80u : 0u;   // bf16x2 (1,1) or 0

    const uint32_t kb_lane = (uint32_t)((lane & 7) * TPITCH + (lane >> 3) * 16);
    const uint32_t kwoff = (uint32_t)(kw * 64 * TPITCH);

    for (int ci = 0; ci < NCHUNK; ci++) {
        if (ci < NCHUNK - 2)       { CP_WAIT(2); }
        else if (ci == NCHUNK - 2) { CP_WAIT(1); }
        else                       { CP_WAIT(0); }
        __syncthreads();   // chunk ci visible; all warps done with chunk ci-1

        if (ci + 3 < NCHUNK) {   // refill buffer (ci+3)&3 == (ci-1)&3 (just freed)
            char* dst = smem + OFF_K0 + ((ci + 3) & 3) * TILE_B;
            cp_async16(dst + boff, ksrc + (size_t)(ci + 3) * 128 * KW + soff);
            CP_COMMIT();
        }

        const uint32_t kbase = sb + OFF_K0 + (ci & 3) * TILE_B + kwoff + kb_lane;
        const __nv_bfloat16* vc = vbase + ci * 128 + kw * 64 + (lane & 3) * 2;

        #pragma unroll
        for (int s = 0; s < 4; s++) {
            float da0, da1, da2, da3, db0, db1, db2, db3;
            {
                uint32_t r0, r1, r2, r3;
                ldsm_x4(r0, r1, r2, r3, kbase + (2 * s) * (8 * TPITCH));
                mma_f16(da0, da1, da2, da3, A[0][0], A[0][1], A[0][2], A[0][3], r0, r1,
                        0.f, 0.f, 0.f, 0.f);
                mma_f16(da0, da1, da2, da3, A[1][0], A[1][1], A[1][2], A[1][3], r2, r3,
                        da0, da1, da2, da3);
            }
            {
                uint32_t r0, r1, r2, r3;
                ldsm_x4(r0, r1, r2, r3, kbase + (2 * s + 1) * (8 * TPITCH));
                mma_f16(db0, db1, db2, db3, A[0][0], A[0][1], A[0][2], A[0][3], r0, r1,
                        0.f, 0.f, 0.f, 0.f);
                mma_f16(db0, db1, db2, db3, A[1][0], A[1][1], A[1][2], A[1][3], r2, r3,
                        db0, db1, db2, db3);
            }

            uint32_t a0 = cvt_bf2(ex2f(da1), ex2f(da0));
            uint32_t a1 = cvt_bf2(ex2f(da3), ex2f(da2));
            uint32_t a2 = cvt_bf2(ex2f(db1), ex2f(db0));
            uint32_t a3 = cvt_bf2(ex2f(db3), ex2f(db2));

            uint32_t pb0, pb1;
            if (nn < 2) {
                pb0 = *(const uint32_t*)(vc + 16 * s);
                pb1 = *(const uint32_t*)(vc + 16 * s + 8);
            } else {
                pb0 = bconst; pb1 = bconst;
            }

            if (s & 1) mma_bf16(f0, f1, f2, f3, a0, a1, a2, a3, pb0, pb1, f0, f1, f2, f3);
            else       mma_bf16(e0, e1, e2, e3, a0, a1, a2, a3, pb0, pb1, e0, e1, e2, e3);
        }
    }

    // merge dual accumulators, then combine the two key halves via smem
    float c0 = e0 + f0, c1 = e1 + f1, c2 = e2 + f2, c3 = e3 + f3;
    __syncthreads();                      // vb region dead; reuse as reduce buf
    float* red = (float*)(smem + OFF_VH);  // 8 warps x 32 lanes x 4 floats = 4 KB
    if (kw == 1) {
        float4* r4 = (float4*)red;
        r4[wr * 32 + lane] = make_float4(c0, c1, c2, c3);
    }
    __syncthreads();
    if (kw == 0) {
        float4 p = ((const float4*)red)[wr * 32 + lane];
        c0 += p.x; c1 += p.y; c2 += p.z; c3 += p.w;

        const int base = lane & ~3;
        float den0 = __shfl_sync(0xffffffffu, c0, base + 1);
        float den1 = __shfl_sync(0xffffffffu, c2, base + 1);
        if ((lane & 3) == 0) {
            const float g = gamma[0];
            float num0 = c0 + c1;
            float num1 = c2 + c3;
            int r0 = n0 + wr * 16 + (lane >> 2);
            size_t i0 = (size_t)b * N_ + r0;
            size_t i1 = i0 + 8;
            out[i0] = g * (num0 / den0) + g_xbar[i0];
            out[i1] = g * (num1 / den1) + g_xbar[i1];
        }
    }
}

// ---------------------------------------------------------------------------
extern "C" void kernel_launch(void* const* d_in, const int* in_sizes, int n_in,
                              void* d_out, int out_size) {
    const float* x     = (const float*)d_in[0];
    const float* Wq    = (const float*)d_in[1];
    const float* bq    = (const float*)d_in[2];
    const float* Wk    = (const float*)d_in[3];
    const float* bk    = (const float*)d_in[4];
    const float* Wv    = (const float*)d_in[5];
    const float* bv    = (const float*)d_in[6];
    const float* gamma = (const float*)d_in[7];
    float* out = (float*)d_out;

    prep_kernel<<<32, 256>>>(Wv, bv, Wq, Wk);

    cudaFuncSetAttribute(qk_gemm, cudaFuncAttributeMaxDynamicSharedMemorySize, QK_SMEM);
    qk_gemm<<<NROWS / 128, 256, QK_SMEM>>>(x, bq, bk);

    cudaFuncSetAttribute(attn_kernel, cudaFuncAttributeMaxDynamicSharedMemorySize, SMEM_TOT);
    attn_kernel<<<dim3(N_ / 128, B_), 512, SMEM_TOT>>>(gamma, out);
}

// round 16
// speedup vs baseline: 1.0692x; 1.0692x over previous
#include <cuda_runtime.h>
#include <cuda_bf16.h>
#include <cuda_fp16.h>
#include <math.h>
#include <stdint.h>

#define B_    8
#define N_    4096
#define CIN   256
#define CQK   32
#define NROWS (B_ * N_)   // 32768
#define QW    32          // q store: fp16 (log2e-scaled)
#define KW    32          // k store: fp16
#define NCHUNK (N_ / 128) // 32
#define LOG2E 1.4426950408889634f
#define EBIAS 21.0f       // constant softmax bias (folded into QK MMA C operand)
#define ECLMP 14.0f       // exp input clamp: P <= 2^14, kills fp16 inf from
                          // heavy-tailed diagonal logits (quadratic-form tail)

// ---- scratch (device globals; no allocation allowed) ----
__device__ __half g_qs[NROWS * QW];   // 2 MB
__device__ __half g_ks[NROWS * KW];   // 2 MB
__device__ __half g_wh[64 * CIN];     // W split hi: [n][k] (n: Wq cols | Wk cols)
__device__ __half g_wl[64 * CIN];     // W split lo
__device__ __half g_vbh[NROWS];       // vbar hi (fp16)
__device__ __half g_vbl[NROWS];       // vbar lo residual (fp16)
__device__ float g_xbar[NROWS];
__device__ float g_wvbar[CIN];
__device__ float g_bvbar;

// =========================== PTX helpers ===================================
__device__ __forceinline__ uint32_t smem_u32(const void* p) {
    uint32_t a;
    asm("{ .reg .u64 t; cvta.to.shared.u64 t, %1; cvt.u32.u64 %0, t; }"
        : "=r"(a) : "l"(p));
    return a;
}
__device__ __forceinline__ void cp_async16(void* dst, const void* src) {
    uint32_t d = smem_u32(dst);
    asm volatile("cp.async.cg.shared.global [%0], [%1], 16;" :: "r"(d), "l"(src) : "memory");
}
#define CP_COMMIT()  asm volatile("cp.async.commit_group;" ::: "memory")
#define CP_WAIT(n)   asm volatile("cp.async.wait_group %0;" :: "n"(n) : "memory")

__device__ __forceinline__ void ldsm_x4(uint32_t& r0, uint32_t& r1,
                                        uint32_t& r2, uint32_t& r3, uint32_t a) {
    asm volatile("ldmatrix.sync.aligned.m8n8.x4.shared.b16 {%0,%1,%2,%3}, [%4];"
        : "=r"(r0), "=r"(r1), "=r"(r2), "=r"(r3) : "r"(a));
}
__device__ __forceinline__ void mma_f16(float& d0, float& d1, float& d2, float& d3,
    uint32_t a0, uint32_t a1, uint32_t a2, uint32_t a3,
    uint32_t b0, uint32_t b1,
    float c0, float c1, float c2, float c3) {
    asm volatile("mma.sync.aligned.m16n8k16.row.col.f32.f16.f16.f32 "
        "{%0,%1,%2,%3},{%4,%5,%6,%7},{%8,%9},{%10,%11,%12,%13};"
        : "=f"(d0), "=f"(d1), "=f"(d2), "=f"(d3)
        : "r"(a0), "r"(a1), "r"(a2), "r"(a3), "r"(b0), "r"(b1),
          "f"(c0), "f"(c1), "f"(c2), "f"(c3));
}
// clamp to <= ECLMP, pack to fp16x2, exponentiate both halves on MUFU
__device__ __forceinline__ uint32_t ex2_h2c(float lo, float hi) {
    __half2 t = __floats2half2_rn(fminf(lo, ECLMP), fminf(hi, ECLMP));
    uint32_t a = *reinterpret_cast<uint32_t*>(&t), r;
    asm("ex2.approx.f16x2 %0, %1;" : "=r"(r) : "r"(a));
    return r;
}
__device__ __forceinline__ uint32_t pack_h2(float a, float b) {
    __half2 t = __floats2half2_rn(a, b);
    return *reinterpret_cast<uint32_t*>(&t);
}

// =========================== prep kernel ===================================
__global__ __launch_bounds__(256) void prep_kernel(
    const float* __restrict__ Wv, const float* __restrict__ bv,
    const float* __restrict__ Wq, const float* __restrict__ Wk) {
    const int wid = threadIdx.x >> 5, lane = threadIdx.x & 31;
    const int row = blockIdx.x * 8 + wid;
    const float* wr = Wv + (size_t)row * CIN;
    float s = 0.f;
    #pragma unroll
    for (int j = 0; j < 8; j++) s += wr[lane + j * 32];
    #pragma unroll
    for (int off = 16; off > 0; off >>= 1)
        s += __shfl_xor_sync(0xffffffffu, s, off);
    if (lane == 0) g_wvbar[row] = s * (1.f / CIN);

    if (blockIdx.x == 0 && wid == 0) {
        float t = 0.f;
        #pragma unroll
        for (int j = 0; j < 8; j++) t += bv[lane + j * 32];
        #pragma unroll
        for (int off = 16; off > 0; off >>= 1)
            t += __shfl_xor_sync(0xffffffffu, t, off);
        if (lane == 0) g_bvbar = t * (1.f / CIN);
    }

    if (blockIdx.x < 8) {
        const int n = blockIdx.x * 8 + wid;
        const float* wsrc = (n < 32) ? (Wq + n) : (Wk + n - 32);
        #pragma unroll
        for (int j = 0; j < 8; j++) {
            int k = lane + j * 32;
            float v = wsrc[(size_t)k * CQK];
            __half h = __float2half_rn(v);
            g_wh[n * CIN + k] = h;
            g_wl[n * CIN + k] = __float2half_rn(v - __half2float(h));
        }
    }
}

// ======================= Q/K projection GEMM (tensor core) ==================
// 2-term exact fp16-x split: x_hi*W_hi + x_hi*W_lo  (== x_f16 @ W exactly)
#define QPITCH 144
#define OFF_XH 0
#define OFF_WHS 18432
#define OFF_WLS 27648
#define OFF_WVS 36864
#define QK_SMEM 37888

__global__ __launch_bounds__(256, 3) void qk_gemm(
    const float* __restrict__ x,
    const float* __restrict__ bq, const float* __restrict__ bk) {

    extern __shared__ __align__(16) char smem[];
    const uint32_t sb = smem_u32(smem);
    const int tid = threadIdx.x, w = tid >> 5, lane = tid & 31;
    const int m0 = blockIdx.x * 128;

    ((float*)(smem + OFF_WVS))[tid] = g_wvbar[tid];
    __syncthreads();

    float c[8][4];
    #pragma unroll
    for (int i = 0; i < 8; i++)
        #pragma unroll
        for (int j = 0; j < 4; j++) c[i][j] = 0.f;
    float sxr[8], svr[8];
    #pragma unroll
    for (int t = 0; t < 8; t++) { sxr[t] = 0.f; svr[t] = 0.f; }

    const uint32_t abh = sb + OFF_XH + (w * 16 + (lane & 15)) * QPITCH + (lane >> 4) * 16;
    const uint32_t bbh = sb + OFF_WHS + (lane & 7) * QPITCH + (lane >> 3) * 16;
    const uint32_t bbl = sb + OFF_WLS + (lane & 7) * QPITCH + (lane >> 3) * 16;
    const float* wvs = (const float*)(smem + OFF_WVS);

    for (int kc = 0; kc < 4; kc++) {
        #pragma unroll
        for (int t = 0; t < 2; t++) {
            int s2 = t * 256 + tid;
            int n = s2 >> 3, seg = s2 & 7;
            *(uint4*)(smem + OFF_WHS + n * QPITCH + seg * 16) =
                *(const uint4*)(g_wh + n * CIN + kc * 64 + seg * 8);
            *(uint4*)(smem + OFF_WLS + n * QPITCH + seg * 16) =
                *(const uint4*)(g_wl + n * CIN + kc * 64 + seg * 8);
        }
        #pragma unroll
        for (int t = 0; t < 8; t++) {
            int row = t * 16 + (tid >> 4), seg = tid & 15;
            float4 xv = *(const float4*)(x + (size_t)(m0 + row) * CIN + kc * 64 + seg * 4);
            float4 wv = *(const float4*)(wvs + kc * 64 + seg * 4);
            sxr[t] += (xv.x + xv.y) + (xv.z + xv.w);
            svr[t] = fmaf(xv.x, wv.x, fmaf(xv.y, wv.y,
                     fmaf(xv.z, wv.z, fmaf(xv.w, wv.w, svr[t]))));
            *(uint2*)(smem + OFF_XH + row * QPITCH + seg * 8) =
                make_uint2(pack_h2(xv.x, xv.y), pack_h2(xv.z, xv.w));
        }
        __syncthreads();

        #pragma unroll
        for (int kc2 = 0; kc2 < 2; kc2++) {
            uint32_t ah0[4], ah1[4];
            ldsm_x4(ah0[0], ah0[1], ah0[2], ah0[3], abh + kc2 * 64);
            ldsm_x4(ah1[0], ah1[1], ah1[2], ah1[3], abh + kc2 * 64 + 32);
            #pragma unroll
            for (int nt = 0; nt < 8; nt++) {
                uint32_t bh[4], bl[4];
                ldsm_x4(bh[0], bh[1], bh[2], bh[3], bbh + nt * 8 * QPITCH + kc2 * 64);
                ldsm_x4(bl[0], bl[1], bl[2], bl[3], bbl + nt * 8 * QPITCH + kc2 * 64);
                mma_f16(c[nt][0], c[nt][1], c[nt][2], c[nt][3],
                        ah0[0], ah0[1], ah0[2], ah0[3], bh[0], bh[1],
                        c[nt][0], c[nt][1], c[nt][2], c[nt][3]);
                mma_f16(c[nt][0], c[nt][1], c[nt][2], c[nt][3],
                        ah1[0], ah1[1], ah1[2], ah1[3], bh[2], bh[3],
                        c[nt][0], c[nt][1], c[nt][2], c[nt][3]);
                mma_f16(c[nt][0], c[nt][1], c[nt][2], c[nt][3],
                        ah0[0], ah0[1], ah0[2], ah0[3], bl[0], bl[1],
                        c[nt][0], c[nt][1], c[nt][2], c[nt][3]);
                mma_f16(c[nt][0], c[nt][1], c[nt][2], c[nt][3],
                        ah1[0], ah1[1], ah1[2], ah1[3], bl[2], bl[3],
                        c[nt][0], c[nt][1], c[nt][2], c[nt][3]);
            }
        }
        __syncthreads();
    }

    // vbar / xbar writeback (vbar hi/lo fp16 split)
    #pragma unroll
    for (int t = 0; t < 8; t++) {
        float sx = sxr[t], sv = svr[t];
        #pragma unroll
        for (int off = 1; off < 16; off <<= 1) {
            sx += __shfl_xor_sync(0xffffffffu, sx, off);
            sv += __shfl_xor_sync(0xffffffffu, sv, off);
        }
        if ((lane & 15) == 0) {
            int row = m0 + t * 16 + (tid >> 4);
            float vb = sv + g_bvbar;
            __half h = __float2half_rn(vb);
            g_vbh[row] = h;
            g_vbl[row] = __float2half_rn(vb - __half2float(h));
            g_xbar[row] = sx * (1.f / CIN);
        }
    }

    // epilogue: bias, (Q: log2e scale), fp16 stores
    const int r0 = lane >> 2;
    const int cl = (lane & 3) * 2;
    const size_t grow = (size_t)m0 + w * 16 + r0;
    #pragma unroll
    for (int nt = 0; nt < 8; nt++) {
        const int n = nt * 8 + cl;
        if (n < 32) {
            float2 bb = *(const float2*)(bq + n);
            #pragma unroll
            for (int half = 0; half < 2; half++) {
                size_t row = grow + half * 8;
                *(uint32_t*)(g_qs + row * QW + n) =
                    pack_h2((c[nt][2 * half + 0] + bb.x) * LOG2E,
                            (c[nt][2 * half + 1] + bb.y) * LOG2E);
            }
        } else {
            float2 bb = *(const float2*)(bk + n - 32);
            #pragma unroll
            for (int half = 0; half < 2; half++) {
                size_t row = grow + half * 8;
                *(uint32_t*)(g_ks + row * KW + n - 32) =
                    pack_h2(c[nt][2 * half + 0] + bb.x, c[nt][2 * half + 1] + bb.y);
            }
        }
    }
}

// =========================== attention kernel ==============================
// smem: vb_hi(8K) + vb_lo(8K) + ring-4 K tiles [128 rows][40 fp16] (80-B pitch)
#define TPITCH   80
#define TILE_B   (128 * TPITCH)      // 10240
#define OFF_VH   0
#define OFF_VL   8192
#define OFF_K0   16384
#define SMEM_TOT (OFF_K0 + 4 * TILE_B)  // 57344

__global__ __launch_bounds__(256, 3) void attn_kernel(
    const float* __restrict__ gamma, float* __restrict__ out) {

    extern __shared__ __align__(16) char smem[];
    const uint32_t sb = smem_u32(smem);
    const int tid = threadIdx.x, wid = tid >> 5, lane = tid & 31;
    const int b = blockIdx.y, n0 = blockIdx.x * 128;

    int boff[2]; long soff[2];
    #pragma unroll
    for (int t = 0; t < 2; t++) {
        int idx = tid + t * 256;
        int row = idx >> 2, seg = idx & 3;
        boff[t] = row * TPITCH + seg * 16;
        soff[t] = (long)row * KW + seg * 8;
    }

    const __half* ksrc = g_ks + (size_t)b * N_ * KW;

    // prologue: g0 = VH + VL + K0 ; g1 = K1 ; g2 = K2
    // vb arrays: 4096 halfs = 8192 B each -> 512 x 16B segments (2 per thread)
    #pragma unroll
    for (int t = 0; t < 2; t++) {
        cp_async16(smem + OFF_VH + (tid + t * 256) * 16,
                   g_vbh + (size_t)b * N_ + (tid + t * 256) * 8);
        cp_async16(smem + OFF_VL + (tid + t * 256) * 16,
                   g_vbl + (size_t)b * N_ + (tid + t * 256) * 8);
    }
    #pragma unroll
    for (int t = 0; t < 2; t++) cp_async16(smem + OFF_K0 + boff[t], ksrc + soff[t]);
    CP_COMMIT();
    #pragma unroll
    for (int t = 0; t < 2; t++)
        cp_async16(smem + OFF_K0 + TILE_B + boff[t], ksrc + (size_t)128 * KW + soff[t]);
    CP_COMMIT();
    #pragma unroll
    for (int t = 0; t < 2; t++)
        cp_async16(smem + OFF_K0 + 2 * TILE_B + boff[t],
                   ksrc + (size_t)256 * KW + soff[t]);
    CP_COMMIT();

    // persistent q fragments (fp16, m16n8k16 A layout)
    uint32_t A[2][4];
    {
        const __half* q0 =
            g_qs + ((size_t)b * N_ + n0 + wid * 16 + (lane >> 2)) * QW + (lane & 3) * 2;
        #pragma unroll
        for (int s = 0; s < 2; s++) {
            A[s][0] = *(const uint32_t*)(q0 + s * 16);
            A[s][1] = *(const uint32_t*)(q0 + s * 16 + 8 * QW);
            A[s][2] = *(const uint32_t*)(q0 + s * 16 + 8);
            A[s][3] = *(const uint32_t*)(q0 + s * 16 + 8 * QW + 8);
        }
    }

    // PV accumulator: C[r][n]: n0/1 = num(hi/lo parts), n2 = den (ones column)
    float c0 = 0.f, c1 = 0.f, c2 = 0.f, c3 = 0.f;
    const float mB = -EBIAS;   // constant softmax bias, folded into QK MMA C

    const int nn = lane >> 2;
    const __half* vbase =
        (nn == 0) ? (const __half*)(smem + OFF_VH)
                  : (const __half*)(smem + OFF_VL);
    const uint32_t bconst = (nn == 2) ? 0x3C003C00u : 0u;   // fp16x2 (1,1) or 0

    const uint32_t kb_lane = (uint32_t)((lane & 7) * TPITCH + (lane >> 3) * 16);

    for (int ci = 0; ci < NCHUNK; ci++) {
        if (ci < NCHUNK - 2)       { CP_WAIT(2); }
        else if (ci == NCHUNK - 2) { CP_WAIT(1); }
        else                       { CP_WAIT(0); }
        __syncthreads();   // chunk ci visible; all warps done with chunk ci-1

        if (ci + 3 < NCHUNK) {   // refill buffer (ci+3)&3 == (ci-1)&3 (just freed)
            char* dst = smem + OFF_K0 + ((ci + 3) & 3) * TILE_B;
            const __half* src = ksrc + (size_t)(ci + 3) * 128 * KW;
            #pragma unroll
            for (int t = 0; t < 2; t++) cp_async16(dst + boff[t], src + soff[t]);
            CP_COMMIT();
        }

        const uint32_t kbase = sb + OFF_K0 + (ci & 3) * TILE_B + kb_lane;
        const __half* vc = vbase + ci * 128 + (lane & 3) * 2;

        #pragma unroll
        for (int s = 0; s < 8; s++) {
            float da0, da1, da2, da3, db0, db1, db2, db3;
            {
                uint32_t r0, r1, r2, r3;
                ldsm_x4(r0, r1, r2, r3, kbase + (2 * s) * (8 * TPITCH));
                mma_f16(da0, da1, da2, da3, A[0][0], A[0][1], A[0][2], A[0][3], r0, r1,
                        mB, mB, mB, mB);
                mma_f16(da0, da1, da2, da3, A[1][0], A[1][1], A[1][2], A[1][3], r2, r3,
                        da0, da1, da2, da3);
            }
            {
                uint32_t r0, r1, r2, r3;
                ldsm_x4(r0, r1, r2, r3, kbase + (2 * s + 1) * (8 * TPITCH));
                mma_f16(db0, db1, db2, db3, A[0][0], A[0][1], A[0][2], A[0][3], r0, r1,
                        mB, mB, mB, mB);
                mma_f16(db0, db1, db2, db3, A[1][0], A[1][1], A[1][2], A[1][3], r2, r3,
                        db0, db1, db2, db3);
            }

            // softmax numerators: clamped fp16x2 exp -> fp16 P fragments
            uint32_t a0 = ex2_h2c(da0, da1);   // row r,   keys 16s+2(l&3)+{0,1}
            uint32_t a1 = ex2_h2c(da2, da3);   // row r+8
            uint32_t a2 = ex2_h2c(db0, db1);   // row r,   keys +8
            uint32_t a3 = ex2_h2c(db2, db3);   // row r+8

            uint32_t pb0, pb1;
            if (nn < 2) {
                pb0 = *(const uint32_t*)(vc + 16 * s);
                pb1 = *(const uint32_t*)(vc + 16 * s + 8);
            } else {
                pb0 = bconst; pb1 = bconst;
            }

            mma_f16(c0, c1, c2, c3, a0, a1, a2, a3, pb0, pb1, c0, c1, c2, c3);
        }
    }

    const int base = lane & ~3;
    float den0 = __shfl_sync(0xffffffffu, c0, base + 1);
    float den1 = __shfl_sync(0xffffffffu, c2, base + 1);
    if ((lane & 3) == 0) {
        const float g = gamma[0];
        float num0 = c0 + c1;
        float num1 = c2 + c3;
        int r0 = n0 + wid * 16 + (lane >> 2);
        size_t i0 = (size_t)b * N_ + r0;
        size_t i1 = i0 + 8;
        out[i0] = g * (num0 / den0) + g_xbar[i0];
        out[i1] = g * (num1 / den1) + g_xbar[i1];
    }
}

// ---------------------------------------------------------------------------
extern "C" void kernel_launch(void* const* d_in, const int* in_sizes, int n_in,
                              void* d_out, int out_size) {
    const float* x     = (const float*)d_in[0];
    const float* Wq    = (const float*)d_in[1];
    const float* bq    = (const float*)d_in[2];
    const float* Wk    = (const float*)d_in[3];
    const float* bk    = (const float*)d_in[4];
    const float* Wv    = (const float*)d_in[5];
    const float* bv    = (const float*)d_in[6];
    const float* gamma = (const float*)d_in[7];
    float* out = (float*)d_out;

    prep_kernel<<<32, 256>>>(Wv, bv, Wq, Wk);

    cudaFuncSetAttribute(qk_gemm, cudaFuncAttributeMaxDynamicSharedMemorySize, QK_SMEM);
    qk_gemm<<<NROWS / 128, 256, QK_SMEM>>>(x, bq, bk);

    cudaFuncSetAttribute(attn_kernel, cudaFuncAttributeMaxDynamicSharedMemorySize, SMEM_TOT);
    attn_kernel<<<dim3(N_ / 128, B_), 256, SMEM_TOT>>>(gamma, out);
}

// round 17
// speedup vs baseline: 1.1063x; 1.0347x over previous
#include <cuda_runtime.h>
#include <cuda_bf16.h>
#include <cuda_fp16.h>
#include <math.h>
#include <stdint.h>

#define B_    8
#define N_    4096
#define CIN   256
#define CQK   32
#define NROWS (B_ * N_)   // 32768
#define QW    32          // q store: fp16 (log2e-scaled)
#define KW    32          // k store: fp16
#define NCHUNK (N_ / 128) // 32
#define LOG2E 1.4426950408889634f
#define EBIAS 21.0f       // constant softmax bias (folded into QK MMA C operand)
#define ECLMP 14.0f       // exp input clamp (kills fp16 inf from diagonal logits)

// ---- scratch (device globals; no allocation allowed) ----
__device__ __half g_qs[NROWS * QW];   // 2 MB
__device__ __half g_ks[NROWS * KW];   // 2 MB
__device__ __half g_wh[64 * CIN];     // W split hi: [n][k] (n: Wq cols | Wk cols)
__device__ __half g_wl[64 * CIN];     // W split lo
__device__ __half g_vbh[NROWS];       // vbar hi (fp16)
__device__ __half g_vbl[NROWS];       // vbar lo residual (fp16)
__device__ float g_xbar[NROWS];
__device__ float g_wvbar[CIN];
__device__ float g_bvbar;

// =========================== PTX helpers ===================================
__device__ __forceinline__ uint32_t smem_u32(const void* p) {
    uint32_t a;
    asm("{ .reg .u64 t; cvta.to.shared.u64 t, %1; cvt.u32.u64 %0, t; }"
        : "=r"(a) : "l"(p));
    return a;
}
__device__ __forceinline__ void cp_async16(void* dst, const void* src) {
    uint32_t d = smem_u32(dst);
    asm volatile("cp.async.cg.shared.global [%0], [%1], 16;" :: "r"(d), "l"(src) : "memory");
}
#define CP_COMMIT()  asm volatile("cp.async.commit_group;" ::: "memory")
#define CP_WAIT(n)   asm volatile("cp.async.wait_group %0;" :: "n"(n) : "memory")

__device__ __forceinline__ void ldsm_x4(uint32_t& r0, uint32_t& r1,
                                        uint32_t& r2, uint32_t& r3, uint32_t a) {
    asm volatile("ldmatrix.sync.aligned.m8n8.x4.shared.b16 {%0,%1,%2,%3}, [%4];"
        : "=r"(r0), "=r"(r1), "=r"(r2), "=r"(r3) : "r"(a));
}
__device__ __forceinline__ void mma_f16(float& d0, float& d1, float& d2, float& d3,
    uint32_t a0, uint32_t a1, uint32_t a2, uint32_t a3,
    uint32_t b0, uint32_t b1,
    float c0, float c1, float c2, float c3) {
    asm volatile("mma.sync.aligned.m16n8k16.row.col.f32.f16.f16.f32 "
        "{%0,%1,%2,%3},{%4,%5,%6,%7},{%8,%9},{%10,%11,%12,%13};"
        : "=f"(d0), "=f"(d1), "=f"(d2), "=f"(d3)
        : "r"(a0), "r"(a1), "r"(a2), "r"(a3), "r"(b0), "r"(b1),
          "f"(c0), "f"(c1), "f"(c2), "f"(c3));
}
// clamp to <= ECLMP, pack to fp16x2, exponentiate both halves on MUFU
__device__ __forceinline__ uint32_t ex2_h2c(float lo, float hi) {
    __half2 t = __floats2half2_rn(fminf(lo, ECLMP), fminf(hi, ECLMP));
    uint32_t a = *reinterpret_cast<uint32_t*>(&t), r;
    asm("ex2.approx.f16x2 %0, %1;" : "=r"(r) : "r"(a));
    return r;
}
__device__ __forceinline__ uint32_t pack_h2(float a, float b) {
    __half2 t = __floats2half2_rn(a, b);
    return *reinterpret_cast<uint32_t*>(&t);
}

// =========================== prep kernel ===================================
__global__ __launch_bounds__(256) void prep_kernel(
    const float* __restrict__ Wv, const float* __restrict__ bv,
    const float* __restrict__ Wq, const float* __restrict__ Wk) {
    const int wid = threadIdx.x >> 5, lane = threadIdx.x & 31;
    const int row = blockIdx.x * 8 + wid;
    const float* wr = Wv + (size_t)row * CIN;
    float s = 0.f;
    #pragma unroll
    for (int j = 0; j < 8; j++) s += wr[lane + j * 32];
    #pragma unroll
    for (int off = 16; off > 0; off >>= 1)
        s += __shfl_xor_sync(0xffffffffu, s, off);
    if (lane == 0) g_wvbar[row] = s * (1.f / CIN);

    if (blockIdx.x == 0 && wid == 0) {
        float t = 0.f;
        #pragma unroll
        for (int j = 0; j < 8; j++) t += bv[lane + j * 32];
        #pragma unroll
        for (int off = 16; off > 0; off >>= 1)
            t += __shfl_xor_sync(0xffffffffu, t, off);
        if (lane == 0) g_bvbar = t * (1.f / CIN);
    }

    if (blockIdx.x < 8) {
        const int n = blockIdx.x * 8 + wid;
        const float* wsrc = (n < 32) ? (Wq + n) : (Wk + n - 32);
        #pragma unroll
        for (int j = 0; j < 8; j++) {
            int k = lane + j * 32;
            float v = wsrc[(size_t)k * CQK];
            __half h = __float2half_rn(v);
            g_wh[n * CIN + k] = h;
            g_wl[n * CIN + k] = __float2half_rn(v - __half2float(h));
        }
    }
}

// ======================= Q/K projection GEMM (tensor core) ==================
// 2-term exact fp16-x split: x_hi*W_hi + x_hi*W_lo  (== x_f16 @ W exactly)
#define QPITCH 144
#define OFF_XH 0
#define OFF_WHS 18432
#define OFF_WLS 27648
#define OFF_WVS 36864
#define QK_SMEM 37888

__global__ __launch_bounds__(256, 3) void qk_gemm(
    const float* __restrict__ x,
    const float* __restrict__ bq, const float* __restrict__ bk) {

    extern __shared__ __align__(16) char smem[];
    const uint32_t sb = smem_u32(smem);
    const int tid = threadIdx.x, w = tid >> 5, lane = tid & 31;
    const int m0 = blockIdx.x * 128;

    ((float*)(smem + OFF_WVS))[tid] = g_wvbar[tid];
    __syncthreads();

    float c[8][4];
    #pragma unroll
    for (int i = 0; i < 8; i++)
        #pragma unroll
        for (int j = 0; j < 4; j++) c[i][j] = 0.f;
    float sxr[8], svr[8];
    #pragma unroll
    for (int t = 0; t < 8; t++) { sxr[t] = 0.f; svr[t] = 0.f; }

    const uint32_t abh = sb + OFF_XH + (w * 16 + (lane & 15)) * QPITCH + (lane >> 4) * 16;
    const uint32_t bbh = sb + OFF_WHS + (lane & 7) * QPITCH + (lane >> 3) * 16;
    const uint32_t bbl = sb + OFF_WLS + (lane & 7) * QPITCH + (lane >> 3) * 16;
    const float* wvs = (const float*)(smem + OFF_WVS);

    for (int kc = 0; kc < 4; kc++) {
        #pragma unroll
        for (int t = 0; t < 2; t++) {
            int s2 = t * 256 + tid;
            int n = s2 >> 3, seg = s2 & 7;
            *(uint4*)(smem + OFF_WHS + n * QPITCH + seg * 16) =
                *(const uint4*)(g_wh + n * CIN + kc * 64 + seg * 8);
            *(uint4*)(smem + OFF_WLS + n * QPITCH + seg * 16) =
                *(const uint4*)(g_wl + n * CIN + kc * 64 + seg * 8);
        }
        #pragma unroll
        for (int t = 0; t < 8; t++) {
            int row = t * 16 + (tid >> 4), seg = tid & 15;
            float4 xv = *(const float4*)(x + (size_t)(m0 + row) * CIN + kc * 64 + seg * 4);
            float4 wv = *(const float4*)(wvs + kc * 64 + seg * 4);
            sxr[t] += (xv.x + xv.y) + (xv.z + xv.w);
            svr[t] = fmaf(xv.x, wv.x, fmaf(xv.y, wv.y,
                     fmaf(xv.z, wv.z, fmaf(xv.w, wv.w, svr[t]))));
            *(uint2*)(smem + OFF_XH + row * QPITCH + seg * 8) =
                make_uint2(pack_h2(xv.x, xv.y), pack_h2(xv.z, xv.w));
        }
        __syncthreads();

        #pragma unroll
        for (int kc2 = 0; kc2 < 2; kc2++) {
            uint32_t ah0[4], ah1[4];
            ldsm_x4(ah0[0], ah0[1], ah0[2], ah0[3], abh + kc2 * 64);
            ldsm_x4(ah1[0], ah1[1], ah1[2], ah1[3], abh + kc2 * 64 + 32);
            #pragma unroll
            for (int nt = 0; nt < 8; nt++) {
                uint32_t bh[4], bl[4];
                ldsm_x4(bh[0], bh[1], bh[2], bh[3], bbh + nt * 8 * QPITCH + kc2 * 64);
                ldsm_x4(bl[0], bl[1], bl[2], bl[3], bbl + nt * 8 * QPITCH + kc2 * 64);
                mma_f16(c[nt][0], c[nt][1], c[nt][2], c[nt][3],
                        ah0[0], ah0[1], ah0[2], ah0[3], bh[0], bh[1],
                        c[nt][0], c[nt][1], c[nt][2], c[nt][3]);
                mma_f16(c[nt][0], c[nt][1], c[nt][2], c[nt][3],
                        ah1[0], ah1[1], ah1[2], ah1[3], bh[2], bh[3],
                        c[nt][0], c[nt][1], c[nt][2], c[nt][3]);
                mma_f16(c[nt][0], c[nt][1], c[nt][2], c[nt][3],
                        ah0[0], ah0[1], ah0[2], ah0[3], bl[0], bl[1],
                        c[nt][0], c[nt][1], c[nt][2], c[nt][3]);
                mma_f16(c[nt][0], c[nt][1], c[nt][2], c[nt][3],
                        ah1[0], ah1[1], ah1[2], ah1[3], bl[2], bl[3],
                        c[nt][0], c[nt][1], c[nt][2], c[nt][3]);
            }
        }
        __syncthreads();
    }

    // vbar / xbar writeback (vbar hi/lo fp16 split)
    #pragma unroll
    for (int t = 0; t < 8; t++) {
        float sx = sxr[t], sv = svr[t];
        #pragma unroll
        for (int off = 1; off < 16; off <<= 1) {
            sx += __shfl_xor_sync(0xffffffffu, sx, off);
            sv += __shfl_xor_sync(0xffffffffu, sv, off);
        }
        if ((lane & 15) == 0) {
            int row = m0 + t * 16 + (tid >> 4);
            float vb = sv + g_bvbar;
            __half h = __float2half_rn(vb);
            g_vbh[row] = h;
            g_vbl[row] = __float2half_rn(vb - __half2float(h));
            g_xbar[row] = sx * (1.f / CIN);
        }
    }

    // epilogue: bias, (Q: log2e scale), fp16 stores
    const int r0 = lane >> 2;
    const int cl = (lane & 3) * 2;
    const size_t grow = (size_t)m0 + w * 16 + r0;
    #pragma unroll
    for (int nt = 0; nt < 8; nt++) {
        const int n = nt * 8 + cl;
        if (n < 32) {
            float2 bb = *(const float2*)(bq + n);
            #pragma unroll
            for (int half = 0; half < 2; half++) {
                size_t row = grow + half * 8;
                *(uint32_t*)(g_qs + row * QW + n) =
                    pack_h2((c[nt][2 * half + 0] + bb.x) * LOG2E,
                            (c[nt][2 * half + 1] + bb.y) * LOG2E);
            }
        } else {
            float2 bb = *(const float2*)(bk + n - 32);
            #pragma unroll
            for (int half = 0; half < 2; half++) {
                size_t row = grow + half * 8;
                *(uint32_t*)(g_ks + row * KW + n - 32) =
                    pack_h2(c[nt][2 * half + 0] + bb.x, c[nt][2 * half + 1] + bb.y);
            }
        }
    }
}

// =========================== attention kernel ==============================
// 128 threads, 4 warps x 32 q-rows: every ldmatrix'd K fragment feeds TWO
// A row-groups -> per-CTA smem LDSM traffic halved vs 8x16 layout.
// smem: vb_hi(8K) + vb_lo(8K) + ring-4 K tiles [128 rows][40 fp16] (80-B pitch)
#define TPITCH   80
#define TILE_B   (128 * TPITCH)      // 10240
#define OFF_VH   0
#define OFF_VL   8192
#define OFF_K0   16384
#define SMEM_TOT (OFF_K0 + 4 * TILE_B)  // 57344

__global__ __launch_bounds__(128, 3) void attn_kernel(
    const float* __restrict__ gamma, float* __restrict__ out) {

    extern __shared__ __align__(16) char smem[];
    const uint32_t sb = smem_u32(smem);
    const int tid = threadIdx.x, wid = tid >> 5, lane = tid & 31;
    const int b = blockIdx.y, n0 = blockIdx.x * 128;

    // per-thread cp.async offsets: K tile = 512 16B segs -> 4 per thread
    int boff[4]; long soff[4];
    #pragma unroll
    for (int t = 0; t < 4; t++) {
        int idx = tid + t * 128;
        int row = idx >> 2, seg = idx & 3;
        boff[t] = row * TPITCH + seg * 16;
        soff[t] = (long)row * KW + seg * 8;
    }

    const __half* ksrc = g_ks + (size_t)b * N_ * KW;

    // prologue: g0 = VH + VL + K0 ; g1 = K1 ; g2 = K2
    // vb arrays: 512 x 16B segments each -> 4 per thread
    #pragma unroll
    for (int t = 0; t < 4; t++) {
        cp_async16(smem + OFF_VH + (tid + t * 128) * 16,
                   g_vbh + (size_t)b * N_ + (tid + t * 128) * 8);
        cp_async16(smem + OFF_VL + (tid + t * 128) * 16,
                   g_vbl + (size_t)b * N_ + (tid + t * 128) * 8);
    }
    #pragma unroll
    for (int t = 0; t < 4; t++) cp_async16(smem + OFF_K0 + boff[t], ksrc + soff[t]);
    CP_COMMIT();
    #pragma unroll
    for (int t = 0; t < 4; t++)
        cp_async16(smem + OFF_K0 + TILE_B + boff[t], ksrc + (size_t)128 * KW + soff[t]);
    CP_COMMIT();
    #pragma unroll
    for (int t = 0; t < 4; t++)
        cp_async16(smem + OFF_K0 + 2 * TILE_B + boff[t],
                   ksrc + (size_t)256 * KW + soff[t]);
    CP_COMMIT();

    // persistent q fragments: 2 row-groups (rows wid*32+g*16 + {r, r+8})
    uint32_t A[2][2][4];
    {
        const __half* qb =
            g_qs + ((size_t)b * N_ + n0 + wid * 32 + (lane >> 2)) * QW + (lane & 3) * 2;
        #pragma unroll
        for (int g = 0; g < 2; g++) {
            const __half* q0 = qb + (size_t)g * 16 * QW;
            #pragma unroll
            for (int s = 0; s < 2; s++) {
                A[g][s][0] = *(const uint32_t*)(q0 + s * 16);
                A[g][s][1] = *(const uint32_t*)(q0 + s * 16 + 8 * QW);
                A[g][s][2] = *(const uint32_t*)(q0 + s * 16 + 8);
                A[g][s][3] = *(const uint32_t*)(q0 + s * 16 + 8 * QW + 8);
            }
        }
    }

    // PV accumulators per row-group: n0/1 = num(hi/lo), n2 = den (ones col)
    float c[2][4];
    #pragma unroll
    for (int g = 0; g < 2; g++)
        #pragma unroll
        for (int j = 0; j < 4; j++) c[g][j] = 0.f;
    const float mB = -EBIAS;

    const int nn = lane >> 2;
    const __half* vbase =
        (nn == 0) ? (const __half*)(smem + OFF_VH)
                  : (const __half*)(smem + OFF_VL);
    const uint32_t bconst = (nn == 2) ? 0x3C003C00u : 0u;   // fp16x2 (1,1) or 0

    const uint32_t kb_lane = (uint32_t)((lane & 7) * TPITCH + (lane >> 3) * 16);

    for (int ci = 0; ci < NCHUNK; ci++) {
        if (ci < NCHUNK - 2)       { CP_WAIT(2); }
        else if (ci == NCHUNK - 2) { CP_WAIT(1); }
        else                       { CP_WAIT(0); }
        __syncthreads();   // chunk ci visible; all warps done with chunk ci-1

        if (ci + 3 < NCHUNK) {   // refill buffer (ci+3)&3 == (ci-1)&3 (just freed)
            char* dst = smem + OFF_K0 + ((ci + 3) & 3) * TILE_B;
            const __half* src = ksrc + (size_t)(ci + 3) * 128 * KW;
            #pragma unroll
            for (int t = 0; t < 4; t++) cp_async16(dst + boff[t], src + soff[t]);
            CP_COMMIT();
        }

        const uint32_t kbase = sb + OFF_K0 + (ci & 3) * TILE_B + kb_lane;
        const __half* vc = vbase + ci * 128 + (lane & 3) * 2;

        #pragma unroll
        for (int s = 0; s < 8; s++) {
            // one pair of K-fragment loads feeds BOTH row-groups
            uint32_t r0, r1, r2, r3, r4, r5, r6, r7;
            ldsm_x4(r0, r1, r2, r3, kbase + (2 * s) * (8 * TPITCH));
            ldsm_x4(r4, r5, r6, r7, kbase + (2 * s + 1) * (8 * TPITCH));

            uint32_t pb0, pb1;
            if (nn < 2) {
                pb0 = *(const uint32_t*)(vc + 16 * s);
                pb1 = *(const uint32_t*)(vc + 16 * s + 8);
            } else {
                pb0 = bconst; pb1 = bconst;
            }

            #pragma unroll
            for (int g = 0; g < 2; g++) {
                float da0, da1, da2, da3, db0, db1, db2, db3;
                mma_f16(da0, da1, da2, da3,
                        A[g][0][0], A[g][0][1], A[g][0][2], A[g][0][3], r0, r1,
                        mB, mB, mB, mB);
                mma_f16(da0, da1, da2, da3,
                        A[g][1][0], A[g][1][1], A[g][1][2], A[g][1][3], r2, r3,
                        da0, da1, da2, da3);
                mma_f16(db0, db1, db2, db3,
                        A[g][0][0], A[g][0][1], A[g][0][2], A[g][0][3], r4, r5,
                        mB, mB, mB, mB);
                mma_f16(db0, db1, db2, db3,
                        A[g][1][0], A[g][1][1], A[g][1][2], A[g][1][3], r6, r7,
                        db0, db1, db2, db3);

                uint32_t a0 = ex2_h2c(da0, da1);
                uint32_t a1 = ex2_h2c(da2, da3);
                uint32_t a2 = ex2_h2c(db0, db1);
                uint32_t a3 = ex2_h2c(db2, db3);

                mma_f16(c[g][0], c[g][1], c[g][2], c[g][3],
                        a0, a1, a2, a3, pb0, pb1,
                        c[g][0], c[g][1], c[g][2], c[g][3]);
            }
        }
    }

    // epilogue: per row-group, den sits in col 2 (lane base+1 holds it)
    const int base = lane & ~3;
    const float gma = gamma[0];
    #pragma unroll
    for (int g = 0; g < 2; g++) {
        float den0 = __shfl_sync(0xffffffffu, c[g][0], base + 1);
        float den1 = __shfl_sync(0xffffffffu, c[g][2], base + 1);
        if ((lane & 3) == 0) {
            float num0 = c[g][0] + c[g][1];
            float num1 = c[g][2] + c[g][3];
            int r0 = n0 + wid * 32 + g * 16 + (lane >> 2);
            size_t i0 = (size_t)b * N_ + r0;
            size_t i1 = i0 + 8;
            out[i0] = gma * (num0 / den0) + g_xbar[i0];
            out[i1] = gma * (num1 / den1) + g_xbar[i1];
        }
    }
}

// ---------------------------------------------------------------------------
extern "C" void kernel_launch(void* const* d_in, const int* in_sizes, int n_in,
                              void* d_out, int out_size) {
    const float* x     = (const float*)d_in[0];
    const float* Wq    = (const float*)d_in[1];
    const float* bq    = (const float*)d_in[2];
    const float* Wk    = (const float*)d_in[3];
    const float* bk    = (const float*)d_in[4];
    const float* Wv    = (const float*)d_in[5];
    const float* bv    = (const float*)d_in[6];
    const float* gamma = (const float*)d_in[7];
    float* out = (float*)d_out;

    prep_kernel<<<32, 256>>>(Wv, bv, Wq, Wk);

    cudaFuncSetAttribute(qk_gemm, cudaFuncAttributeMaxDynamicSharedMemorySize, QK_SMEM);
    qk_gemm<<<NROWS / 128, 256, QK_SMEM>>>(x, bq, bk);

    cudaFuncSetAttribute(attn_kernel, cudaFuncAttributeMaxDynamicSharedMemorySize, SMEM_TOT);
    attn_kernel<<<dim3(N_ / 128, B_), 128, SMEM_TOT>>>(gamma, out);
}